// round 1
// baseline (speedup 1.0000x reference)
#include <cuda_runtime.h>

// CustomMaskedConv1D: out[b,l,g,o] = sum_k mask(b,l,k) * sum_i X[b,l+k-2,g*64+i] * W[g,o,i,k]
// mask(b,l,k) = (pos[b,l+k-2] - (l+k-2) == pos[b,l] - l), X zero-padded outside [0,L)

constexpr int Bb  = 4;
constexpr int Ll  = 4096;
constexpr int Cc  = 1024;
constexpr int Gg  = 16;
constexpr int IPG = 64;
constexpr int OPG = 64;
constexpr int KK  = 5;
constexpr int TL  = 128;                 // l-rows per CTA

constexpr int XS_ROWS  = TL + 4;                    // 132
constexpr int XS_ELEMS = XS_ROWS * IPG;             // 8448 floats
constexpr int WS_ELEMS = KK * IPG * OPG;            // 20480 floats
constexpr int SMEM_BYTES = (XS_ELEMS + WS_ELEMS) * 4 + XS_ROWS * 4;  // 116240 B

__device__ __forceinline__ unsigned long long pk2(float x, float y) {
    unsigned long long r;
    asm("mov.b64 %0, {%1, %2};" : "=l"(r)
        : "r"(__float_as_uint(x)), "r"(__float_as_uint(y)));
    return r;
}

__device__ __forceinline__ void upk2(unsigned long long v, float& x, float& y) {
    unsigned a, b;
    asm("mov.b64 {%0, %1}, %2;" : "=r"(a), "=r"(b) : "l"(v));
    x = __uint_as_float(a);
    y = __uint_as_float(b);
}

// packed fp32x2 FMA (FFMA2) — sm_100+ PTX
__device__ __forceinline__ unsigned long long f2fma(unsigned long long a,
                                                    unsigned long long b,
                                                    unsigned long long c) {
    unsigned long long d;
    asm("fma.rn.f32x2 %0, %1, %2, %3;" : "=l"(d) : "l"(a), "l"(b), "l"(c));
    return d;
}

__global__ __launch_bounds__(256)
void masked_conv1d_kernel(const float* __restrict__ x,
                          const int*   __restrict__ pos,
                          const float* __restrict__ w,
                          float*       __restrict__ out) {
    extern __shared__ float sm[];
    float* Xs = sm;                                  // [132][64]
    float* Ws = sm + XS_ELEMS;                       // [5][64][64]  (k, i, o)
    int*   dq = (int*)(sm + XS_ELEMS + WS_ELEMS);    // [132]  pos[gl]-gl (or sentinel)

    const int l0  = blockIdx.x * TL;
    const int g   = blockIdx.y;
    const int b   = blockIdx.z;
    const int tid = threadIdx.x;

    // ---- stage X tile (zero-padded), float4 coalesced ----
    const float* xg = x + (size_t)b * Ll * Cc + g * IPG;
    for (int idx = tid; idx < XS_ROWS * 16; idx += 256) {
        int j  = idx >> 4;
        int i4 = idx & 15;
        int gl = l0 - 2 + j;
        float4 v = make_float4(0.f, 0.f, 0.f, 0.f);
        if (gl >= 0 && gl < Ll)
            v = *(const float4*)(xg + (size_t)gl * Cc + i4 * 4);
        *(float4*)(Xs + j * IPG + i4 * 4) = v;
    }

    // ---- stage W[g]: gmem linear (o,i,k) -> smem [k][i][o], coalesced reads ----
    const float* wg = w + (size_t)g * WS_ELEMS;
    for (int idx = tid; idx < WS_ELEMS; idx += 256) {
        float v   = wg[idx];                // idx = o*320 + i*5 + k
        int   k   = idx % 5;
        int   rem = idx / 5;
        int   i   = rem & 63;
        int   o   = rem >> 6;
        Ws[(k * IPG + i) * OPG + o] = v;
    }

    // ---- stage position deltas: dq[j] = pos[gl] - gl  (OOB -> -1-gl, never matches) ----
    for (int j = tid; j < XS_ROWS; j += 256) {
        int gl = l0 - 2 + j;
        dq[j] = (gl >= 0 && gl < Ll) ? (pos[b * Ll + gl] - gl) : (-1 - gl);
    }
    __syncthreads();

    // ---- compute: thread = 8 l-rows x 4 o-cols (as 8x2 f32x2) ----
    const int ty = tid >> 4;      // 0..15 -> rows ty*8
    const int tx = tid & 15;      // 0..15 -> cols tx*4
    const int r0 = ty * 8;

    int dd[12];
#pragma unroll
    for (int j = 0; j < 12; j++) dd[j] = dq[r0 + j];

    unsigned long long c2[8][2];
#pragma unroll
    for (int m = 0; m < 8; m++) { c2[m][0] = 0ull; c2[m][1] = 0ull; }

    for (int k = 0; k < KK; k++) {
        // mask(l,k) is i-invariant: run the pure GEMM slice, apply mask at the end
        unsigned long long t2[8][2];
#pragma unroll
        for (int m = 0; m < 8; m++) { t2[m][0] = 0ull; t2[m][1] = 0ull; }

        const float* wk = Ws + k * IPG * OPG + tx * 4;
        const float* xk = Xs + (r0 + k) * IPG;

#pragma unroll 4
        for (int i = 0; i < IPG; i++) {
            float4 bv = *(const float4*)(wk + i * OPG);
            unsigned long long b01 = pk2(bv.x, bv.y);
            unsigned long long b23 = pk2(bv.z, bv.w);
#pragma unroll
            for (int m = 0; m < 8; m++) {
                float a = xk[m * IPG + i];          // smem broadcast across tx
                unsigned long long aa = pk2(a, a);
                t2[m][0] = f2fma(aa, b01, t2[m][0]);
                t2[m][1] = f2fma(aa, b23, t2[m][1]);
            }
        }

#pragma unroll
        for (int m = 0; m < 8; m++) {
            float mk = (dd[m + k] == dd[m + 2]) ? 1.0f : 0.0f;
            unsigned long long mm = pk2(mk, mk);
            c2[m][0] = f2fma(mm, t2[m][0], c2[m][0]);
            c2[m][1] = f2fma(mm, t2[m][1], c2[m][1]);
        }
    }

    // ---- store: (B,L,G,OPG), float4 per row ----
    float* og = out + (((size_t)b * Ll + l0 + r0) * Gg + g) * OPG + tx * 4;
#pragma unroll
    for (int m = 0; m < 8; m++) {
        float v0, v1, v2, v3;
        upk2(c2[m][0], v0, v1);
        upk2(c2[m][1], v2, v3);
        *(float4*)(og + (size_t)m * Gg * OPG) = make_float4(v0, v1, v2, v3);
    }
}

extern "C" void kernel_launch(void* const* d_in, const int* in_sizes, int n_in,
                              void* d_out, int out_size) {
    const float* x   = (const float*)d_in[0];
    const int*   pos = (const int*)d_in[1];
    const float* w   = (const float*)d_in[2];
    float*       out = (float*)d_out;

    cudaFuncSetAttribute(masked_conv1d_kernel,
                         cudaFuncAttributeMaxDynamicSharedMemorySize, SMEM_BYTES);

    dim3 grid(Ll / TL, Gg, Bb);   // (32, 16, 4)
    masked_conv1d_kernel<<<grid, 256, SMEM_BYTES>>>(x, pos, w, out);
}

// round 3
// speedup vs baseline: 4.0825x; 4.0825x over previous
#include <cuda_runtime.h>
#include <cuda_bf16.h>

// out[b,l,g,o] = sum_k mask(b,l,k) * sum_i X[b,l+k-2,g*64+i] * W[g,o,i,k]
// mask(l,k) = (pos[l+k-2]-(l+k-2) == pos[l]-l); X zero-padded outside [0,L).
// Legacy tensor-core path (mma.sync bf16, sm_80+ ISA — compiles at base sm_103).
// bf16 hi/lo 3-pass split: X*W ≈ Xh*Wh + Xh*Wl + Xl*Wh   (fp32 accumulate)

constexpr int Bb = 4, Ll = 4096, Cc = 1024, Gg = 16, IPG = 64, OPG = 64, KK = 5, TL = 128;
constexpr int PADH = 72;          // halfs per smem row (144 B) -> conflict-free ldmatrix
constexpr int ROWB = PADH * 2;    // 144 bytes
constexpr int A_ROWS = TL + 4;    // 132

// pre-split W: [g][k][o][i] bf16 hi / lo
__device__ __nv_bfloat16 g_Whi[Gg * KK * OPG * IPG];
__device__ __nv_bfloat16 g_Wlo[Gg * KK * OPG * IPG];

// smem byte offsets
constexpr int SA_H = 0;
constexpr int SA_L = SA_H + A_ROWS * ROWB;          // 19008
constexpr int SB_H = SA_L + A_ROWS * ROWB;          // 38016
constexpr int SB_L = SB_H + OPG * ROWB;             // 47232
constexpr int S_DQ = SB_L + OPG * ROWB;             // 56448
constexpr int SMEM_BYTES = S_DQ + A_ROWS * 4 + 16;  // ~57 KB

__device__ __forceinline__ unsigned smem_u32(const void* p) {
    unsigned a;
    asm("{ .reg .u64 t; cvta.to.shared.u64 t, %1; cvt.u32.u64 %0, t; }" : "=r"(a) : "l"(p));
    return a;
}

// f32 pair -> packed bf16 hi + packed bf16 lo (residual)
__device__ __forceinline__ void hilo2(float a, float b, unsigned& h, unsigned& l) {
    asm("cvt.rn.bf16x2.f32 %0, %1, %2;" : "=r"(h) : "f"(b), "f"(a));   // {hi:b, lo:a}
    float ha = __uint_as_float(h << 16);
    float hb = __uint_as_float(h & 0xffff0000u);
    float la = a - ha, lb = b - hb;
    asm("cvt.rn.bf16x2.f32 %0, %1, %2;" : "=r"(l) : "f"(lb), "f"(la));
}

__device__ __forceinline__ void sts64(unsigned addr, unsigned r0, unsigned r1) {
    asm volatile("st.shared.v2.b32 [%0], {%1, %2};" :: "r"(addr), "r"(r0), "r"(r1) : "memory");
}
__device__ __forceinline__ void sts128(unsigned addr, uint4 v) {
    asm volatile("st.shared.v4.b32 [%0], {%1, %2, %3, %4};"
                 :: "r"(addr), "r"(v.x), "r"(v.y), "r"(v.z), "r"(v.w) : "memory");
}
__device__ __forceinline__ void ldsm4(unsigned addr, unsigned& r0, unsigned& r1,
                                      unsigned& r2, unsigned& r3) {
    asm volatile("ldmatrix.sync.aligned.m8n8.x4.shared.b16 {%0, %1, %2, %3}, [%4];"
                 : "=r"(r0), "=r"(r1), "=r"(r2), "=r"(r3) : "r"(addr));
}
__device__ __forceinline__ void mma16816(float& c0, float& c1, float& c2, float& c3,
                                         unsigned a0, unsigned a1, unsigned a2, unsigned a3,
                                         unsigned b0, unsigned b1) {
    asm volatile("mma.sync.aligned.m16n8k16.row.col.f32.bf16.bf16.f32 "
                 "{%0,%1,%2,%3}, {%4,%5,%6,%7}, {%8,%9}, {%0,%1,%2,%3};"
                 : "+f"(c0), "+f"(c1), "+f"(c2), "+f"(c3)
                 : "r"(a0), "r"(a1), "r"(a2), "r"(a3), "r"(b0), "r"(b1));
}

// ---- pre-kernel: W (g,o,i,k) f32 -> (g,k,o,i) bf16 hi/lo ----
__global__ void prep_w(const float* __restrict__ w) {
    int idx = blockIdx.x * 256 + threadIdx.x;
    if (idx >= Gg * KK * OPG * IPG) return;
    int i = idx & 63;
    int r = idx >> 6;
    int o = r & 63;
    int r2 = r >> 6;
    int k = r2 % KK;
    int g = r2 / KK;
    float v = w[(((g * OPG + o) * IPG + i) * KK) + k];
    __nv_bfloat16 hb = __float2bfloat16(v);
    __nv_bfloat16 lb = __float2bfloat16(v - __bfloat162float(hb));
    g_Whi[idx] = hb;
    g_Wlo[idx] = lb;
}

__global__ __launch_bounds__(256, 2)
void masked_conv1d_hmma(const float* __restrict__ x,
                        const int*   __restrict__ pos,
                        float*       __restrict__ out) {
    extern __shared__ char sm[];
    const unsigned smb = smem_u32(sm);
    const int l0 = blockIdx.x * TL, g = blockIdx.y, b = blockIdx.z;
    const int tid = threadIdx.x;
    const int wid = tid >> 5, lane = tid & 31;

    // ---- stage position deltas (OOB rows are zero in X, sentinel value irrelevant) ----
    int* dq = (int*)(sm + S_DQ);
    for (int j = tid; j < A_ROWS; j += 256) {
        int gl = l0 - 2 + j;
        dq[j] = (gl >= 0 && gl < Ll) ? (pos[b * Ll + gl] - gl) : (int)0x80000000 + j;
    }

    // ---- stage X tile once: f32 -> bf16 hi/lo, padded rows ----
    const float* xg = x + (size_t)b * Ll * Cc + g * IPG;
    for (int idx = tid; idx < A_ROWS * 16; idx += 256) {
        int j  = idx >> 4;        // staged row
        int i4 = idx & 15;        // which float4 of 16
        int gl = l0 - 2 + j;
        float4 v = make_float4(0.f, 0.f, 0.f, 0.f);
        if (gl >= 0 && gl < Ll)
            v = *(const float4*)(xg + (size_t)gl * Cc + i4 * 4);
        unsigned h0, h1, e0, e1;
        hilo2(v.x, v.y, h0, e0);
        hilo2(v.z, v.w, h1, e1);
        unsigned off = j * ROWB + i4 * 8;
        sts64(smb + SA_H + off, h0, h1);
        sts64(smb + SA_L + off, e0, e1);
    }

    // ---- accumulators: 8 n-tiles x 4 f32 ----
    float c[8][4];
#pragma unroll
    for (int nt = 0; nt < 8; nt++)
#pragma unroll
        for (int e = 0; e < 4; e++) c[nt][e] = 0.f;

    const int lr0 = wid * 16 + (lane >> 2);   // output rows: lr0, lr0+8
    const int seg = lane >> 3;
    const int l8  = lane & 7;

#pragma unroll
    for (int k = 0; k < KK; k++) {
        __syncthreads();
        // ---- stage W slice k (hi+lo) ----
        {
            const uint4* wh = (const uint4*)(g_Whi + (size_t)(g * KK + k) * (OPG * IPG));
            const uint4* wl = (const uint4*)(g_Wlo + (size_t)(g * KK + k) * (OPG * IPG));
#pragma unroll
            for (int t = 0; t < 2; t++) {
                int ch = tid + t * 256;               // 512 x 16B chunks
                int o  = ch >> 3, sg = ch & 7;
                unsigned off = o * ROWB + sg * 16;
                sts128(smb + SB_H + off, wh[ch]);
                sts128(smb + SB_L + off, wl[ch]);
            }
        }
        __syncthreads();

        // row masks for this conv-k (rows lr0 and lr0+8)
        const bool m0 = (dq[lr0 + k] == dq[lr0 + 2]);
        const bool m1 = (dq[lr0 + 8 + k] == dq[lr0 + 8 + 2]);

        // A ldmatrix address pattern: matrices (r0-7,c0-7),(r8-15,c0-7),(r0-7,c8-15),(r8-15,c8-15)
        const unsigned arow = wid * 16 + k + l8 + ((seg & 1) << 3);
        // B ldmatrix pattern: (n0-7,k0-7),(n0-7,k8-15),(n8-15,k0-7),(n8-15,k8-15)
        const unsigned brow_add = l8 + ((seg >> 1) << 3);
        const unsigned bcol_add = (seg & 1) << 3;

#pragma unroll
        for (int q = 0; q < 4; q++) {              // 16-wide i-chunks
            const unsigned acol = q * 16 + ((seg >> 1) << 3);
            unsigned aaddr = smb + SA_H + arow * ROWB + acol * 2;
            unsigned ah0, ah1, ah2, ah3, al0, al1, al2, al3;
            ldsm4(aaddr, ah0, ah1, ah2, ah3);
            ldsm4(aaddr + (SA_L - SA_H), al0, al1, al2, al3);
            // apply row mask
            ah0 = m0 ? ah0 : 0u;  ah2 = m0 ? ah2 : 0u;
            ah1 = m1 ? ah1 : 0u;  ah3 = m1 ? ah3 : 0u;
            al0 = m0 ? al0 : 0u;  al2 = m0 ? al2 : 0u;
            al1 = m1 ? al1 : 0u;  al3 = m1 ? al3 : 0u;

#pragma unroll
            for (int p = 0; p < 4; p++) {          // pairs of n-tiles
                unsigned baddr = smb + SB_H + (p * 16 + brow_add) * ROWB
                               + (q * 16 + bcol_add) * 2;
                unsigned bh0, bh1, bh2, bh3;
                ldsm4(baddr, bh0, bh1, bh2, bh3);
                mma16816(c[p*2][0], c[p*2][1], c[p*2][2], c[p*2][3],
                         ah0, ah1, ah2, ah3, bh0, bh1);
                mma16816(c[p*2+1][0], c[p*2+1][1], c[p*2+1][2], c[p*2+1][3],
                         ah0, ah1, ah2, ah3, bh2, bh3);
                mma16816(c[p*2][0], c[p*2][1], c[p*2][2], c[p*2][3],
                         al0, al1, al2, al3, bh0, bh1);
                mma16816(c[p*2+1][0], c[p*2+1][1], c[p*2+1][2], c[p*2+1][3],
                         al0, al1, al2, al3, bh2, bh3);

                unsigned bl0, bl1, bl2, bl3;
                ldsm4(baddr + (SB_L - SB_H), bl0, bl1, bl2, bl3);
                mma16816(c[p*2][0], c[p*2][1], c[p*2][2], c[p*2][3],
                         ah0, ah1, ah2, ah3, bl0, bl1);
                mma16816(c[p*2+1][0], c[p*2+1][1], c[p*2+1][2], c[p*2+1][3],
                         ah0, ah1, ah2, ah3, bl2, bl3);
            }
        }
    }

    // ---- epilogue: c frag (r=lr0 cols 2j, r=lr0+8) -> out (B,L,G,OPG) ----
    const int ocol = (lane & 3) * 2;
    float* o0 = out + (((size_t)b * Ll + l0 + lr0) * Gg + g) * OPG + ocol;
    float* o1 = o0 + 8 * Gg * OPG;
#pragma unroll
    for (int nt = 0; nt < 8; nt++) {
        *(float2*)(o0 + nt * 8) = make_float2(c[nt][0], c[nt][1]);
        *(float2*)(o1 + nt * 8) = make_float2(c[nt][2], c[nt][3]);
    }
}

extern "C" void kernel_launch(void* const* d_in, const int* in_sizes, int n_in,
                              void* d_out, int out_size) {
    const float* x   = (const float*)d_in[0];
    const int*   pos = (const int*)d_in[1];
    const float* w   = (const float*)d_in[2];
    float*       out = (float*)d_out;

    prep_w<<<(Gg * KK * OPG * IPG + 255) / 256, 256>>>(w);

    cudaFuncSetAttribute(masked_conv1d_hmma,
                         cudaFuncAttributeMaxDynamicSharedMemorySize, SMEM_BYTES);
    dim3 grid(Ll / TL, Gg, Bb);   // (32, 16, 4)
    masked_conv1d_hmma<<<grid, 256, SMEM_BYTES>>>(x, pos, out);
}

// round 4
// speedup vs baseline: 4.2663x; 1.0450x over previous
#include <cuda_runtime.h>
#include <cuda_bf16.h>

// out[b,l,g,o] = sum_k mask(b,l,k) * sum_i X[b,l+k-2,g*64+i] * W[g,o,i,k]
// mask(l,k) = (pos[l+k-2]-(l+k-2) == pos[l]-l); X zero-padded outside [0,L).
// mma.sync bf16 3-pass hi/lo split (AhBh + AlBh + AhBl), fp32 accumulate.
// Warp tile M=32xN=64, swizzled smem, cp.async double-buffered W staging.

constexpr int Bb = 4, Ll = 4096, Cc = 1024, Gg = 16, IPG = 64, OPG = 64, KK = 5, TL = 128;
constexpr int A_ROWS = TL + 4;    // 132

// pre-split W: [g][k][o][i] bf16 hi / lo
__device__ __nv_bfloat16 g_Whi[Gg * KK * OPG * IPG];
__device__ __nv_bfloat16 g_Wlo[Gg * KK * OPG * IPG];

// smem layout (bytes): rows of 128B, SW128 swizzled inside each region
constexpr int SA_H  = 0;                       // A hi: 132 x 128B
constexpr int SA_L  = A_ROWS * 128;            // 16896: A lo
constexpr int SB    = 2 * A_ROWS * 128;        // 33792: B double buffer
constexpr int B_LO  = 8192;                    // lo half within a B buffer
constexpr int B_BUF = 16384;                   // hi 8K + lo 8K
constexpr int S_DQ  = SB + 2 * B_BUF;          // 66560
constexpr int SMEM_BYTES = S_DQ + A_ROWS * 4 + 32;   // ~67.1 KB -> 3 CTAs/SM

__device__ __forceinline__ unsigned smem_u32(const void* p) {
    unsigned a;
    asm("{ .reg .u64 t; cvta.to.shared.u64 t, %1; cvt.u32.u64 %0, t; }" : "=r"(a) : "l"(p));
    return a;
}
__device__ __forceinline__ unsigned sw128(unsigned off) { return off ^ ((off >> 3) & 0x70); }

// f32 pair -> packed bf16 hi + packed bf16 lo (residual)
__device__ __forceinline__ void hilo2(float a, float b, unsigned& h, unsigned& l) {
    asm("cvt.rn.bf16x2.f32 %0, %1, %2;" : "=r"(h) : "f"(b), "f"(a));   // {hi:b, lo:a}
    float ha = __uint_as_float(h << 16);
    float hb = __uint_as_float(h & 0xffff0000u);
    float la = a - ha, lb = b - hb;
    asm("cvt.rn.bf16x2.f32 %0, %1, %2;" : "=r"(l) : "f"(lb), "f"(la));
}

__device__ __forceinline__ void sts64(unsigned addr, unsigned r0, unsigned r1) {
    asm volatile("st.shared.v2.b32 [%0], {%1, %2};" :: "r"(addr), "r"(r0), "r"(r1) : "memory");
}
__device__ __forceinline__ void ldsm4(unsigned addr, unsigned& r0, unsigned& r1,
                                      unsigned& r2, unsigned& r3) {
    asm volatile("ldmatrix.sync.aligned.m8n8.x4.shared.b16 {%0, %1, %2, %3}, [%4];"
                 : "=r"(r0), "=r"(r1), "=r"(r2), "=r"(r3) : "r"(addr));
}
__device__ __forceinline__ void mma16816(float* c,
                                         unsigned a0, unsigned a1, unsigned a2, unsigned a3,
                                         unsigned b0, unsigned b1) {
    asm volatile("mma.sync.aligned.m16n8k16.row.col.f32.bf16.bf16.f32 "
                 "{%0,%1,%2,%3}, {%4,%5,%6,%7}, {%8,%9}, {%0,%1,%2,%3};"
                 : "+f"(c[0]), "+f"(c[1]), "+f"(c[2]), "+f"(c[3])
                 : "r"(a0), "r"(a1), "r"(a2), "r"(a3), "r"(b0), "r"(b1));
}
__device__ __forceinline__ void cp16(unsigned dst, const void* src) {
    asm volatile("cp.async.cg.shared.global [%0], [%1], 16;" :: "r"(dst), "l"(src) : "memory");
}

// ---- pre-kernel: W (g,o,i,k) f32 -> (g,k,o,i) bf16 hi/lo ----
__global__ void prep_w(const float* __restrict__ w) {
    int idx = blockIdx.x * 256 + threadIdx.x;
    if (idx >= Gg * KK * OPG * IPG) return;
    int i = idx & 63;
    int r = idx >> 6;
    int o = r & 63;
    int r2 = r >> 6;
    int k = r2 % KK;
    int g = r2 / KK;
    float v = w[(((g * OPG + o) * IPG + i) * KK) + k];
    __nv_bfloat16 hb = __float2bfloat16(v);
    __nv_bfloat16 lb = __float2bfloat16(v - __bfloat162float(hb));
    g_Whi[idx] = hb;
    g_Wlo[idx] = lb;
}

// stage W slice k (hi+lo) into B buffer via cp.async; one commit_group
__device__ __forceinline__ void stage_B_async(unsigned smb, int buf, int k, int g, int tid) {
    const char* wh = (const char*)(g_Whi + (size_t)(g * KK + k) * (OPG * IPG));
    const char* wl = (const char*)(g_Wlo + (size_t)(g * KK + k) * (OPG * IPG));
    unsigned base = smb + SB + buf * B_BUF;
#pragma unroll
    for (int t = 0; t < 4; t++) {
        int ch = tid + t * 128;                // 512 x 16B chunks per half
        unsigned sw = sw128((unsigned)ch * 16);
        cp16(base + sw, wh + ch * 16);
        cp16(base + B_LO + sw, wl + ch * 16);
    }
    asm volatile("cp.async.commit_group;" ::: "memory");
}

__global__ __launch_bounds__(128, 3)
void masked_conv1d_hmma(const float* __restrict__ x,
                        const int*   __restrict__ pos,
                        float*       __restrict__ out) {
    extern __shared__ char sm[];
    const unsigned smb = smem_u32(sm);
    const int l0 = blockIdx.x * TL, g = blockIdx.y, b = blockIdx.z;
    const int tid = threadIdx.x;
    const int wid = tid >> 5, lane = tid & 31;

    // kick off W slice 0 immediately
    stage_B_async(smb, 0, 0, g, tid);

    // ---- position deltas (OOB neighbors get unique sentinels; center row is always valid) ----
    int* dq = (int*)(sm + S_DQ);
    for (int j = tid; j < A_ROWS; j += 128) {
        int gl = l0 - 2 + j;
        dq[j] = (gl >= 0 && gl < Ll) ? (pos[b * Ll + gl] - gl) : (int)0x80000000 + j;
    }

    // ---- stage X tile: f32 -> bf16 hi/lo, swizzled 128B rows ----
    const float* xg = x + (size_t)b * Ll * Cc + g * IPG;
    for (int idx = tid; idx < A_ROWS * 16; idx += 128) {
        int j  = idx >> 4;        // staged row
        int i4 = idx & 15;        // which float4 of 16
        int gl = l0 - 2 + j;
        float4 v = make_float4(0.f, 0.f, 0.f, 0.f);
        if (gl >= 0 && gl < Ll)
            v = *(const float4*)(xg + (size_t)gl * Cc + i4 * 4);
        unsigned h0, h1, e0, e1;
        hilo2(v.x, v.y, h0, e0);
        hilo2(v.z, v.w, h1, e1);
        unsigned sw = sw128((unsigned)(j * 128 + i4 * 8));
        sts64(smb + SA_H + sw, h0, h1);
        sts64(smb + SA_L + sw, e0, e1);
    }

    // ---- accumulators: 2 M-tiles x 8 N-tiles x 4 ----
    float c[2][8][4];
#pragma unroll
    for (int mt = 0; mt < 2; mt++)
#pragma unroll
        for (int nt = 0; nt < 8; nt++)
#pragma unroll
            for (int e = 0; e < 4; e++) c[mt][nt][e] = 0.f;

    const int lane8 = lane & 7, seg = lane >> 3;
    const int rbase = wid * 32 + (lane >> 2);        // this thread's base output row
    const unsigned acoff = (unsigned)((seg >> 1) << 3);
    const unsigned brow  = (unsigned)(lane8 + ((seg >> 1) << 3));
    const unsigned bcoff = (unsigned)((seg & 1) << 3);

#pragma unroll
    for (int k = 0; k < KK; k++) {
        asm volatile("cp.async.wait_group 0;" ::: "memory");
        __syncthreads();                               // W(k) visible; prev buf free
        if (k < KK - 1) stage_B_async(smb, (k + 1) & 1, k + 1, g, tid);
        const unsigned bbase = smb + SB + (k & 1) * B_BUF;

        // row masks for this conv-k (4 rows per thread: +0,+8,+16,+24)
        const bool m0 = (dq[rbase + k]      == dq[rbase + 2]);
        const bool m1 = (dq[rbase + 8 + k]  == dq[rbase + 8 + 2]);
        const bool m2 = (dq[rbase + 16 + k] == dq[rbase + 16 + 2]);
        const bool m3 = (dq[rbase + 24 + k] == dq[rbase + 24 + 2]);

        const unsigned arow0 = (unsigned)(wid * 32 + k + lane8 + ((seg & 1) << 3));

#pragma unroll
        for (int q = 0; q < 4; q++) {                  // 16-wide i-chunks
            unsigned ah[8], al[8];
            unsigned a0 = smb + SA_H + sw128(arow0 * 128 + (q * 16 + acoff) * 2);
            unsigned a1 = smb + SA_H + sw128((arow0 + 16) * 128 + (q * 16 + acoff) * 2);
            ldsm4(a0, ah[0], ah[1], ah[2], ah[3]);
            ldsm4(a1, ah[4], ah[5], ah[6], ah[7]);
            ldsm4(a0 + (SA_L - SA_H), al[0], al[1], al[2], al[3]);
            ldsm4(a1 + (SA_L - SA_H), al[4], al[5], al[6], al[7]);
            // row-granular mask
            ah[0] = m0 ? ah[0] : 0u;  ah[2] = m0 ? ah[2] : 0u;
            ah[1] = m1 ? ah[1] : 0u;  ah[3] = m1 ? ah[3] : 0u;
            ah[4] = m2 ? ah[4] : 0u;  ah[6] = m2 ? ah[6] : 0u;
            ah[5] = m3 ? ah[5] : 0u;  ah[7] = m3 ? ah[7] : 0u;
            al[0] = m0 ? al[0] : 0u;  al[2] = m0 ? al[2] : 0u;
            al[1] = m1 ? al[1] : 0u;  al[3] = m1 ? al[3] : 0u;
            al[4] = m2 ? al[4] : 0u;  al[6] = m2 ? al[6] : 0u;
            al[5] = m3 ? al[5] : 0u;  al[7] = m3 ? al[7] : 0u;

#pragma unroll
            for (int p = 0; p < 4; p++) {              // pairs of N-tiles
                unsigned baddr = bbase + sw128((p * 16 + brow) * 128 + (q * 16 + bcoff) * 2);
                unsigned bh0, bh1, bh2, bh3, bl0, bl1, bl2, bl3;
                ldsm4(baddr, bh0, bh1, bh2, bh3);
                ldsm4(baddr + B_LO, bl0, bl1, bl2, bl3);
#pragma unroll
                for (int mt = 0; mt < 2; mt++) {
                    mma16816(c[mt][p*2],   ah[mt*4], ah[mt*4+1], ah[mt*4+2], ah[mt*4+3], bh0, bh1);
                    mma16816(c[mt][p*2+1], ah[mt*4], ah[mt*4+1], ah[mt*4+2], ah[mt*4+3], bh2, bh3);
                    mma16816(c[mt][p*2],   al[mt*4], al[mt*4+1], al[mt*4+2], al[mt*4+3], bh0, bh1);
                    mma16816(c[mt][p*2+1], al[mt*4], al[mt*4+1], al[mt*4+2], al[mt*4+3], bh2, bh3);
                    mma16816(c[mt][p*2],   ah[mt*4], ah[mt*4+1], ah[mt*4+2], ah[mt*4+3], bl0, bl1);
                    mma16816(c[mt][p*2+1], ah[mt*4], ah[mt*4+1], ah[mt*4+2], ah[mt*4+3], bl2, bl3);
                }
            }
        }
    }

    // ---- epilogue: fragments -> out (B,L,G,OPG) ----
    const int ocol = (lane & 3) * 2;
#pragma unroll
    for (int mt = 0; mt < 2; mt++) {
        const int row0 = l0 + wid * 32 + mt * 16 + (lane >> 2);
        float* o0 = out + (((size_t)b * Ll + row0) * Gg + g) * OPG + ocol;
        float* o1 = o0 + (size_t)8 * Gg * OPG;
#pragma unroll
        for (int nt = 0; nt < 8; nt++) {
            *(float2*)(o0 + nt * 8) = make_float2(c[mt][nt][0], c[mt][nt][1]);
            *(float2*)(o1 + nt * 8) = make_float2(c[mt][nt][2], c[mt][nt][3]);
        }
    }
}

extern "C" void kernel_launch(void* const* d_in, const int* in_sizes, int n_in,
                              void* d_out, int out_size) {
    const float* x   = (const float*)d_in[0];
    const int*   pos = (const int*)d_in[1];
    const float* w   = (const float*)d_in[2];
    float*       out = (float*)d_out;

    prep_w<<<(Gg * KK * OPG * IPG + 255) / 256, 256>>>(w);

    cudaFuncSetAttribute(masked_conv1d_hmma,
                         cudaFuncAttributeMaxDynamicSharedMemorySize, SMEM_BYTES);
    dim3 grid(Ll / TL, Gg, Bb);   // (32, 16, 4)
    masked_conv1d_hmma<<<grid, 128, SMEM_BYTES>>>(x, pos, out);
}